// round 1
// baseline (speedup 1.0000x reference)
#include <cuda_runtime.h>
#include <cstdint>

// ---------------------------------------------------------------------------
// TorchNeighborList: N=4096 atoms, no PBC. Output layout (as float32):
//   [0,      M)   idx_i   (sentinel N in padding)
//   [M,     2M)   idx_j
//   [2M,    5M)   Rij     (row-major [M,3]; pos[neighbor]-pos[center])
//   [5M,    8M)   cell_offset (all zeros)
//   [8M,    9M)   mask    (1.0 valid / 0.0 padding)
//   [9M]          num_pairs
// where M = 2P = N*(N-1).
//
// Ordering reproduced analytically: centers ascending; within center k,
// neighbors in order j = (k+t) mod N for t = 1..N-1 (this is exactly what
// the reference's stable argsort over concat(triu_i, triu_j) produces).
// ---------------------------------------------------------------------------

#define MAX_N 8192

__device__ int g_counts[MAX_N];
__device__ int g_offsets[MAX_N];

// exact (non-contracted) squared distance, matching jnp.linalg.norm assoc order
__device__ __forceinline__ float dist2(float dx, float dy, float dz) {
    return __fadd_rn(__fadd_rn(__fmul_rn(dx, dx), __fmul_rn(dy, dy)),
                     __fmul_rn(dz, dz));
}

// -------- Kernel 1: bulk default fill (write-bound, ~604 MB) --------------
__global__ __launch_bounds__(256) void fill_defaults(float4* __restrict__ out4,
                                                     size_t n4, size_t idx_end4,
                                                     float sentinel) {
    const float4 sv = make_float4(sentinel, sentinel, sentinel, sentinel);
    const float4 zv = make_float4(0.f, 0.f, 0.f, 0.f);
    size_t stride = (size_t)gridDim.x * blockDim.x;
    for (size_t i = (size_t)blockIdx.x * blockDim.x + threadIdx.x; i < n4;
         i += stride) {
        out4[i] = (i < idx_end4) ? sv : zv;
    }
}

// -------- Kernel 2: per-center neighbor counts ----------------------------
__global__ __launch_bounds__(256) void count_kernel(const float* __restrict__ pos,
                                                    int N) {
    extern __shared__ float sp[];  // x[N], y[N], z[N]
    for (int i = threadIdx.x; i < N; i += blockDim.x) {
        sp[i]         = pos[3 * i + 0];
        sp[N + i]     = pos[3 * i + 1];
        sp[2 * N + i] = pos[3 * i + 2];
    }
    __syncthreads();
    int k = blockIdx.x * blockDim.x + threadIdx.x;
    if (k >= N) return;
    float xk = sp[k], yk = sp[N + k], zk = sp[2 * N + k];
    int cnt = 0;
    for (int j = 0; j < N; j++) {
        float dx = __fsub_rn(sp[j], xk);
        float dy = __fsub_rn(sp[N + j], yk);
        float dz = __fsub_rn(sp[2 * N + j], zk);
        float d2 = dist2(dx, dy, dz);
        cnt += (j != k) && (d2 < 25.0f);
    }
    g_counts[k] = cnt;
}

// -------- Kernel 3: exclusive scan over counts (single block) -------------
__global__ __launch_bounds__(1024) void scan_kernel(float* __restrict__ out,
                                                    size_t M, int N) {
    __shared__ int s[1024];
    int t = threadIdx.x;
    int per = (N + 1023) / 1024;  // items per thread (<=8 for N<=8192)
    int local[8];
    int sum = 0;
    for (int u = 0; u < per; u++) {
        int i = t * per + u;
        int c = (i < N) ? g_counts[i] : 0;
        local[u] = sum;  // thread-local exclusive prefix
        sum += c;
    }
    s[t] = sum;
    __syncthreads();
    // Hillis-Steele inclusive scan
    for (int off = 1; off < 1024; off <<= 1) {
        int v = (t >= off) ? s[t - off] : 0;
        __syncthreads();
        s[t] += v;
        __syncthreads();
    }
    int base = s[t] - sum;  // exclusive prefix for this thread's chunk
    for (int u = 0; u < per; u++) {
        int i = t * per + u;
        if (i < N) g_offsets[i] = base + local[u];
    }
    if (t == 1023) {
        out[9 * M] = (float)s[1023];  // num_pairs
    }
}

// -------- Kernel 4: warp-per-center compacted emit ------------------------
__global__ __launch_bounds__(256) void fill_kernel(const float* __restrict__ pos,
                                                   float* __restrict__ out,
                                                   size_t M, int N) {
    extern __shared__ float sp[];  // x[N], y[N], z[N]
    for (int i = threadIdx.x; i < N; i += blockDim.x) {
        sp[i]         = pos[3 * i + 0];
        sp[N + i]     = pos[3 * i + 1];
        sp[2 * N + i] = pos[3 * i + 2];
    }
    __syncthreads();

    int warp = (int)((blockIdx.x * blockDim.x + threadIdx.x) >> 5);
    int lane = threadIdx.x & 31;
    if (warp >= N) return;
    int k = warp;

    float xk = sp[k], yk = sp[N + k], zk = sp[2 * N + k];
    int base = g_offsets[k];

    float* __restrict__ idx_i = out;
    float* __restrict__ idx_j = out + M;
    float* __restrict__ rij   = out + 2 * M;
    float* __restrict__ maskp = out + 8 * M;
    float fk = (float)k;

    for (int t0 = 1; t0 < N; t0 += 32) {
        int t = t0 + lane;
        bool valid = false;
        int j = 0;
        float dx = 0.f, dy = 0.f, dz = 0.f;
        if (t < N) {
            j = k + t;
            if (j >= N) j -= N;  // order: k+1..N-1 then 0..k-1
            dx = __fsub_rn(sp[j], xk);          // pos[neighbor]-pos[center]
            dy = __fsub_rn(sp[N + j], yk);
            dz = __fsub_rn(sp[2 * N + j], zk);
            float d2 = dist2(dx, dy, dz);
            valid = d2 < 25.0f;
        }
        unsigned m = __ballot_sync(0xffffffffu, valid);
        if (valid) {
            int p = base + __popc(m & ((1u << lane) - 1u));
            idx_i[p] = fk;
            idx_j[p] = (float)j;
            rij[3 * (size_t)p + 0] = dx;
            rij[3 * (size_t)p + 1] = dy;
            rij[3 * (size_t)p + 2] = dz;
            maskp[p] = 1.0f;
        }
        base += __popc(m);
    }
}

// ---------------------------------------------------------------------------
extern "C" void kernel_launch(void* const* d_in, const int* in_sizes, int n_in,
                              void* d_out, int out_size) {
    const float* pos = (const float*)d_in[0];
    int N = in_sizes[0] / 3;                       // 4096
    size_t M = ((size_t)out_size - 1) / 9;         // 2P = N*(N-1)
    float* out = (float*)d_out;

    // 1) defaults: idx regions <- (float)N, everything else <- 0
    size_t n4 = (9 * M) / 4;       // 9M divisible by 4 for even N
    size_t idx_end4 = (2 * M) / 4; // 2M divisible by 4
    fill_defaults<<<2048, 256>>>((float4*)out, n4, idx_end4, (float)N);

    // 2) counts
    size_t smem = (size_t)3 * N * sizeof(float);
    count_kernel<<<(N + 255) / 256, 256, smem>>>(pos, N);

    // 3) scan -> offsets + num_pairs
    scan_kernel<<<1, 1024>>>(out, M, N);

    // 4) compacted emit of valid entries
    int nwarps = N;
    int blocks = (nwarps * 32 + 255) / 256;
    fill_kernel<<<blocks, 256, smem>>>(pos, out, M, N);
}

// round 2
// speedup vs baseline: 1.1972x; 1.1972x over previous
#include <cuda_runtime.h>
#include <cstdint>

// ---------------------------------------------------------------------------
// TorchNeighborList: N=4096 atoms, no PBC. Output layout (as float32):
//   [0,      M)   idx_i   (sentinel N in padding)
//   [M,     2M)   idx_j
//   [2M,    5M)   Rij     (row-major [M,3]; pos[neighbor]-pos[center])
//   [5M,    8M)   cell_offset (all zeros)
//   [8M,    9M)   mask    (1.0 valid / 0.0 padding)
//   [9M]          num_pairs
// where M = 2P = N*(N-1).
//
// Ordering reproduced analytically: centers ascending; within center k,
// neighbors in order j = (k+t) mod N for t = 1..N-1 (exactly what the
// reference's stable argsort over concat(triu_i, triu_j) produces).
//
// Parallel plan: the t-range of each center is split into C chunks of
// CHUNK=512. Counts are per (center, chunk); an order-preserving scan over
// the flattened (k,c) array gives each warp an independent starting offset,
// so the fill pass is 32768 short independent warps (16 ballot steps each).
// ---------------------------------------------------------------------------

#define CHUNK 512
#define MAX_SEG 65536

__device__ int g_counts[MAX_SEG];
__device__ int g_offsets[MAX_SEG];

// exact (non-contracted) squared distance, matching jnp.linalg.norm assoc order
__device__ __forceinline__ float dist2(float dx, float dy, float dz) {
    return __fadd_rn(__fadd_rn(__fmul_rn(dx, dx), __fmul_rn(dy, dy)),
                     __fmul_rn(dz, dz));
}

// -------- Kernel 1: bulk default fill (write-bound, ~604 MB) --------------
__global__ __launch_bounds__(256) void fill_defaults(float4* __restrict__ out4,
                                                     size_t n4, size_t idx_end4,
                                                     float sentinel) {
    const float4 sv = make_float4(sentinel, sentinel, sentinel, sentinel);
    const float4 zv = make_float4(0.f, 0.f, 0.f, 0.f);
    size_t stride = (size_t)gridDim.x * blockDim.x;
    for (size_t i = (size_t)blockIdx.x * blockDim.x + threadIdx.x; i < n4;
         i += stride) {
        __stcs(&out4[i], (i < idx_end4) ? sv : zv);  // streaming: bypass L2 reuse
    }
}

// -------- Kernel 2: per-(center,chunk) neighbor counts (warp each) --------
__global__ __launch_bounds__(256) void count_kernel(const float* __restrict__ pos,
                                                    int N, int C) {
    int warp = (int)((blockIdx.x * (size_t)blockDim.x + threadIdx.x) >> 5);
    int lane = threadIdx.x & 31;
    if (warp >= N * C) return;
    int k = warp / C;
    int c = warp - k * C;

    const float* pk = pos + 3 * (size_t)k;
    float xk = __ldg(pk), yk = __ldg(pk + 1), zk = __ldg(pk + 2);

    int cnt = 0;
    int tbase = c * CHUNK;
#pragma unroll 4
    for (int i = 0; i < CHUNK; i += 32) {
        int t = tbase + i + lane;
        bool valid = false;
        if (t > 0 && t < N) {
            int j = k + t;
            if (j >= N) j -= N;
            const float* pj = pos + 3 * (size_t)j;
            float dx = __fsub_rn(__ldg(pj),     xk);
            float dy = __fsub_rn(__ldg(pj + 1), yk);
            float dz = __fsub_rn(__ldg(pj + 2), zk);
            valid = dist2(dx, dy, dz) < 25.0f;
        }
        cnt += __popc(__ballot_sync(0xffffffffu, valid));
    }
    if (lane == 0) g_counts[warp] = cnt;
}

// -------- Kernel 3: exclusive scan over (center,chunk) counts -------------
__global__ __launch_bounds__(1024) void scan_kernel(float* __restrict__ out,
                                                    size_t M, int S) {
    __shared__ int s[1024];
    int t = threadIdx.x;
    int per = (S + 1023) / 1024;
    int sum = 0;
    for (int u = 0; u < per; u++) {
        int i = t * per + u;
        if (i < S) sum += g_counts[i];
    }
    s[t] = sum;
    __syncthreads();
    // Hillis-Steele inclusive scan over per-thread sums
    for (int off = 1; off < 1024; off <<= 1) {
        int v = (t >= off) ? s[t - off] : 0;
        __syncthreads();
        s[t] += v;
        __syncthreads();
    }
    int base = s[t] - sum;  // exclusive prefix of this thread's span
    for (int u = 0; u < per; u++) {
        int i = t * per + u;
        if (i < S) {
            g_offsets[i] = base;
            base += g_counts[i];
        }
    }
    if (t == 1023) out[9 * M] = (float)s[1023];  // num_pairs
}

// -------- Kernel 4: warp-per-(center,chunk) compacted emit ----------------
__global__ __launch_bounds__(256) void fill_kernel(const float* __restrict__ pos,
                                                   float* __restrict__ out,
                                                   size_t M, int N, int C) {
    int warp = (int)((blockIdx.x * (size_t)blockDim.x + threadIdx.x) >> 5);
    int lane = threadIdx.x & 31;
    if (warp >= N * C) return;
    int k = warp / C;
    int c = warp - k * C;

    const float* pk = pos + 3 * (size_t)k;
    float xk = __ldg(pk), yk = __ldg(pk + 1), zk = __ldg(pk + 2);
    float fk = (float)k;
    int base = g_offsets[warp];

    float* __restrict__ idx_i = out;
    float* __restrict__ idx_j = out + M;
    float* __restrict__ rij   = out + 2 * M;
    float* __restrict__ maskp = out + 8 * M;

    int tbase = c * CHUNK;
#pragma unroll 4
    for (int i = 0; i < CHUNK; i += 32) {
        int t = tbase + i + lane;
        bool valid = false;
        int j = 0;
        float dx = 0.f, dy = 0.f, dz = 0.f;
        if (t > 0 && t < N) {
            j = k + t;
            if (j >= N) j -= N;
            const float* pj = pos + 3 * (size_t)j;
            dx = __fsub_rn(__ldg(pj),     xk);  // pos[neighbor]-pos[center]
            dy = __fsub_rn(__ldg(pj + 1), yk);
            dz = __fsub_rn(__ldg(pj + 2), zk);
            valid = dist2(dx, dy, dz) < 25.0f;
        }
        unsigned m = __ballot_sync(0xffffffffu, valid);
        if (valid) {
            int p = base + __popc(m & ((1u << lane) - 1u));
            idx_i[p] = fk;
            idx_j[p] = (float)j;
            rij[3 * (size_t)p + 0] = dx;
            rij[3 * (size_t)p + 1] = dy;
            rij[3 * (size_t)p + 2] = dz;
            maskp[p] = 1.0f;
        }
        base += __popc(m);
    }
}

// ---------------------------------------------------------------------------
extern "C" void kernel_launch(void* const* d_in, const int* in_sizes, int n_in,
                              void* d_out, int out_size) {
    const float* pos = (const float*)d_in[0];
    int N = in_sizes[0] / 3;                   // 4096
    size_t M = ((size_t)out_size - 1) / 9;     // 2P = N*(N-1)
    float* out = (float*)d_out;

    int C = (N + CHUNK - 1) / CHUNK;           // 8 chunks per center
    int S = N * C;                             // 32768 segments

    // 1) defaults: idx regions <- (float)N, everything else <- 0
    size_t n4 = (9 * M) / 4;       // 9M divisible by 4 for even N
    size_t idx_end4 = (2 * M) / 4;
    fill_defaults<<<2048, 256>>>((float4*)out, n4, idx_end4, (float)N);

    // 2) per-(center,chunk) counts: one warp each
    int threads = S * 32;
    int blocks = (threads + 255) / 256;
    count_kernel<<<blocks, 256>>>(pos, N, C);

    // 3) order-preserving scan -> per-segment offsets + num_pairs
    scan_kernel<<<1, 1024>>>(out, M, S);

    // 4) compacted emit: one warp per (center,chunk)
    fill_kernel<<<blocks, 256>>>(pos, out, M, N, C);
}

// round 4
// speedup vs baseline: 1.2436x; 1.0387x over previous
#include <cuda_runtime.h>
#include <cstdint>

// ---------------------------------------------------------------------------
// TorchNeighborList: N=4096 atoms, no PBC. Output layout (as float32):
//   [0,      M)   idx_i   (valid prefix [0,T), sentinel N in [T,M))
//   [M,     2M)   idx_j   (same split)
//   [2M,    5M)   Rij     (valid prefix [0,3T), zeros after)
//   [5M,    8M)   cell_offset (ALL zeros, independent of T)
//   [8M,    9M)   mask    (1.0 in [0,T), 0.0 after)
//   [9M]          num_pairs = T
// where M = 2P = N*(N-1), T = number of in-cutoff directed pairs.
//
// Ordering reproduced analytically: centers ascending; within center k,
// neighbors in order j = (k+t) mod N for t = 1..N-1 (exactly the reference's
// stable argsort over concat(triu_i, triu_j)).
//
// Schedule:
//   L1 count+zero : warp-per-(center,chunk) counts, PLUS extra blocks that
//                   zero the T-independent cell_offset region (201 MB).
//   L2 scan       : order-preserving exclusive scan -> offsets, T.
//   L3 epilogue   : compacted valid emit || padding-suffix stream (disjoint
//                   address ranges once T is known).
// ---------------------------------------------------------------------------

#define CHUNK 512
#define MAX_SEG 65536

__device__ int g_counts[MAX_SEG];
__device__ int g_offsets[MAX_SEG];
__device__ int g_total;

// exact (non-contracted) squared distance, matching jnp.linalg.norm assoc order
__device__ __forceinline__ float dist2(float dx, float dy, float dz) {
    return __fadd_rn(__fadd_rn(__fmul_rn(dx, dx), __fmul_rn(dy, dy)),
                     __fmul_rn(dz, dz));
}

// -------- Kernel 1: counts + cell_offset zeroing --------------------------
// Blocks [0, FB):       warp per (center,chunk) -> g_counts
// Blocks [FB, gridDim): zero out[5M, 8M) with streaming float4 stores
__global__ __launch_bounds__(256) void count_zero_kernel(
    const float* __restrict__ pos, float* __restrict__ out,
    size_t M, int N, int C, int FB) {
    if ((int)blockIdx.x < FB) {
        int warp = (int)((blockIdx.x * (size_t)blockDim.x + threadIdx.x) >> 5);
        int lane = threadIdx.x & 31;
        if (warp >= N * C) return;
        int k = warp / C;
        int c = warp - k * C;

        const float* pk = pos + 3 * (size_t)k;
        float xk = __ldg(pk), yk = __ldg(pk + 1), zk = __ldg(pk + 2);

        int cnt = 0;
        int tbase = c * CHUNK;
#pragma unroll 4
        for (int i = 0; i < CHUNK; i += 32) {
            int t = tbase + i + lane;
            bool valid = false;
            if (t > 0 && t < N) {
                int j = k + t;
                if (j >= N) j -= N;
                const float* pj = pos + 3 * (size_t)j;
                float dx = __fsub_rn(__ldg(pj),     xk);
                float dy = __fsub_rn(__ldg(pj + 1), yk);
                float dz = __fsub_rn(__ldg(pj + 2), zk);
                valid = dist2(dx, dy, dz) < 25.0f;
            }
            cnt += __popc(__ballot_sync(0xffffffffu, valid));
        }
        if (lane == 0) g_counts[warp] = cnt;
    } else {
        // cell_offset region: [5M, 8M), 4-aligned since M % 4 == 0
        float4* __restrict__ out4 = (float4*)out;
        const float4 zv = make_float4(0.f, 0.f, 0.f, 0.f);
        size_t lo4 = (5 * M) / 4, hi4 = (8 * M) / 4;
        int pb = (int)blockIdx.x - FB;
        int npb = (int)gridDim.x - FB;
        size_t stride = (size_t)npb * blockDim.x;
        for (size_t i = lo4 + (size_t)pb * blockDim.x + threadIdx.x; i < hi4;
             i += stride) {
            __stcs(&out4[i], zv);
        }
    }
}

// -------- Kernel 2: exclusive scan over (center,chunk) counts -------------
__global__ __launch_bounds__(1024) void scan_kernel(float* __restrict__ out,
                                                    size_t M, int S) {
    __shared__ int s[1024];
    int t = threadIdx.x;
    int per = (S + 1023) / 1024;
    int sum = 0;
    for (int u = 0; u < per; u++) {
        int i = t * per + u;
        if (i < S) sum += g_counts[i];
    }
    s[t] = sum;
    __syncthreads();
    for (int off = 1; off < 1024; off <<= 1) {
        int v = (t >= off) ? s[t - off] : 0;
        __syncthreads();
        s[t] += v;
        __syncthreads();
    }
    int base = s[t] - sum;  // exclusive prefix of this thread's span
    for (int u = 0; u < per; u++) {
        int i = t * per + u;
        if (i < S) {
            g_offsets[i] = base;
            base += g_counts[i];
        }
    }
    if (t == 1023) {
        g_total = s[1023];
        out[9 * M] = (float)s[1023];  // num_pairs
    }
}

// -------- Kernel 3: fused epilogue ----------------------------------------
// Blocks [0, FB):       warp-per-(center,chunk) compacted valid emit.
// Blocks [FB, gridDim): stream padding suffix of idx_i/idx_j/Rij/mask
//                       (cell_offset already written in L1).
__global__ __launch_bounds__(256) void epilogue(const float* __restrict__ pos,
                                                float* __restrict__ out,
                                                size_t M, int N, int C, int FB) {
    if ((int)blockIdx.x < FB) {
        // ---- valid-entry emit ----
        int warp = (int)((blockIdx.x * (size_t)blockDim.x + threadIdx.x) >> 5);
        int lane = threadIdx.x & 31;
        if (warp >= N * C) return;
        int k = warp / C;
        int c = warp - k * C;

        const float* pk = pos + 3 * (size_t)k;
        float xk = __ldg(pk), yk = __ldg(pk + 1), zk = __ldg(pk + 2);
        float fk = (float)k;
        int base = g_offsets[warp];

        float* __restrict__ idx_i = out;
        float* __restrict__ idx_j = out + M;
        float* __restrict__ rij   = out + 2 * M;
        float* __restrict__ maskp = out + 8 * M;

        int tbase = c * CHUNK;
#pragma unroll 4
        for (int i = 0; i < CHUNK; i += 32) {
            int t = tbase + i + lane;
            bool valid = false;
            int j = 0;
            float dx = 0.f, dy = 0.f, dz = 0.f;
            if (t > 0 && t < N) {
                j = k + t;
                if (j >= N) j -= N;
                const float* pj = pos + 3 * (size_t)j;
                dx = __fsub_rn(__ldg(pj),     xk);
                dy = __fsub_rn(__ldg(pj + 1), yk);
                dz = __fsub_rn(__ldg(pj + 2), zk);
                valid = dist2(dx, dy, dz) < 25.0f;
            }
            unsigned m = __ballot_sync(0xffffffffu, valid);
            if (valid) {
                int p = base + __popc(m & ((1u << lane) - 1u));
                idx_i[p] = fk;
                idx_j[p] = (float)j;
                rij[3 * (size_t)p + 0] = dx;
                rij[3 * (size_t)p + 1] = dy;
                rij[3 * (size_t)p + 2] = dz;
                maskp[p] = 1.0f;
            }
            base += __popc(m);
        }
    } else {
        // ---- padding suffix writer (skips cell_offset region) ----
        size_t T = (size_t)g_total;        // valid-prefix length
        size_t n4 = (6 * M) / 4;           // idx_i+idx_j+Rij (5M) + mask (1M)
        float4* __restrict__ out4 = (float4*)out;
        float sentinel = (float)N;
        int pb = (int)blockIdx.x - FB;
        int npb = (int)gridDim.x - FB;
        size_t stride = (size_t)npb * blockDim.x;
        for (size_t i = (size_t)pb * blockDim.x + threadIdx.x; i < n4;
             i += stride) {
            size_t f = 4 * i;
            if (f >= 5 * M) f += 3 * M;    // hop over cell_offset into mask
            float val;
            size_t e, bound;
            if (f < 2 * M) {               // idx_i / idx_j
                val = sentinel;
                e = (f < M) ? f : f - M;
                bound = T;
            } else if (f < 5 * M) {        // Rij
                val = 0.f;
                e = f - 2 * M;
                bound = 3 * T;
            } else {                        // mask [8M, 9M)
                val = 0.f;
                e = f - 8 * M;
                bound = T;
            }
            if (e >= bound) {
                __stcs(&out4[f / 4], make_float4(val, val, val, val));
            } else if (e + 4 > bound) {
                // boundary vector (at most one per array): scalar writes
                for (int u = 0; u < 4; u++)
                    if (e + u >= bound) out[f + u] = val;
            }
            // else: inside valid prefix -> owned by emit blocks, skip
        }
    }
}

// ---------------------------------------------------------------------------
extern "C" void kernel_launch(void* const* d_in, const int* in_sizes, int n_in,
                              void* d_out, int out_size) {
    const float* pos = (const float*)d_in[0];
    int N = in_sizes[0] / 3;                   // 4096
    size_t M = ((size_t)out_size - 1) / 9;     // 2P = N*(N-1)
    float* out = (float*)d_out;

    int C = (N + CHUNK - 1) / CHUNK;           // 8 chunks per center
    int S = N * C;                             // 32768 segments

    int fill_blocks = (S * 32 + 255) / 256;    // 4096: warp per segment
    int zero_blocks = 2048;                    // cell_offset zeroing
    int pad_blocks  = 4096;                    // padding stream

    count_zero_kernel<<<fill_blocks + zero_blocks, 256>>>(pos, out, M, N, C,
                                                          fill_blocks);
    scan_kernel<<<1, 1024>>>(out, M, S);
    epilogue<<<fill_blocks + pad_blocks, 256>>>(pos, out, M, N, C, fill_blocks);
}